// round 16
// baseline (speedup 1.0000x reference)
#include <cuda_runtime.h>
#include <cuda_bf16.h>
#include <math.h>
#include <stdint.h>

#define BB 16
#define CC 32
#define HH 224
#define WW 224
#define NPIX (HH*WW)            // 50176
#define CL_PLANE (NPIX*CC)      // channel-last elems per batch
#define NTILES (BB*HH*2)        // 7168 tiles (y rows x two x-halves)

#define KP 296                  // padded K pitch (288+8) elems; 148 words = 20 mod 32 -> ldsm + STS conflict-free
#define LUT_OFF 0               // 64 floats
#define B_OFF 256               // 32*296*2 = 18944 B
#define A_OFF 19456             // 128*296*2 = 75776 B (16-aligned)
#define SMEM_BYTES 95232        // fits 2 CTAs/SM (190464 <= 228KB)
#define DF_PITCH 132            // fp32 bounce pitch (bank-conflict-free)

// ---------------- device scratch (static: allowed) ----------------
__device__ unsigned short g_hx[BB*CL_PLANE];   // x split hi  (channel-last bf16)
__device__ unsigned short g_mx[BB*CL_PLANE];   //         mid
__device__ unsigned short g_lx[BB*CL_PLANE];   //         lo
__device__ unsigned short g_lev[BB*CL_PLANE];  // stage-0 levels, channel-last bf16
__device__ unsigned short g_B1[CC*288];        // conv1 signs, [co][k], k=tap*32+ci
__device__ unsigned short g_B2[CC*288];        // conv2 signs
__device__ float g_lut1[64];                   // t0[32], diff[32]
__device__ float g_lut2[64];

// ---------------------------------------------------------------------------
// Prep (unchanged, validated): signs [co][k] + BN-folded LUT (t0, diff).
// ---------------------------------------------------------------------------
__global__ void prep_kernel(const float* __restrict__ w1, const float* __restrict__ w2,
                            const float* __restrict__ bn1w, const float* __restrict__ bn1b,
                            const float* __restrict__ bn1m, const float* __restrict__ bn1v,
                            const float* __restrict__ bn2w, const float* __restrict__ bn2b,
                            const float* __restrict__ bn2m, const float* __restrict__ bn2v,
                            const float* __restrict__ a1p, const float* __restrict__ a2p,
                            const float* __restrict__ nsp)
{
    __shared__ float mean1[32], mean2[32];
    int t = threadIdx.x;
    if (t < 32) {
        float s = 0.f;
        for (int i = 0; i < 288; i++) s += w1[t*288 + i];
        mean1[t] = s / 288.f;
    } else if (t < 64) {
        int c = t - 32;
        float s = 0.f;
        for (int i = 0; i < 288; i++) s += w2[c*288 + i];
        mean2[c] = s / 288.f;
    }
    __syncthreads();

    for (int idx = t; idx < 9216; idx += blockDim.x) {
        int co  = idx / 288;
        int r   = idx % 288;
        int ci  = r / 9;
        int tap = r % 9;
        int k   = tap*32 + ci;
        g_B1[co*288 + k] = (w1[idx] > mean1[co]) ? 0x3F80 : 0xBF80;
        g_B2[co*288 + k] = (w2[idx] > mean2[co]) ? 0x3F80 : 0xBF80;
    }

    if (t < 32) {
        float a1 = *a1p, a2 = *a2p, ns = *nsp;
        {
            float sd = sqrtf(bn1v[t] + 1e-5f);
            float w  = bn1w[t] / sd;
            float b  = bn1b[t] - w * bn1m[t];
            float l0 = rintf((0.5f*a2 - b) / (a1*w));
            float l1 = rintf((1.5f*a2 - b) / (a1*w));
            g_lut1[t]      = l0;
            g_lut1[32 + t] = l1 - l0;
        }
        {
            float sd = sqrtf(bn2v[t] + 1e-5f);
            float w  = bn2w[t] / sd;
            float b  = bn2b[t] - w * bn2m[t];
            float l0 = rintf((0.5f*ns - b) / (a2*w));
            float l1 = rintf((1.5f*ns - b) / (a2*w));
            g_lut2[t]      = l0;
            g_lut2[32 + t] = l1 - l0;
        }
    }
}

// ---------------------------------------------------------------------------
// Prepass (unchanged, validated): x -> exact 3-way bf16 split, channel-last.
// ---------------------------------------------------------------------------
__global__ void split_kernel(const float* __restrict__ x)
{
    __shared__ float sh[32*225];
    int blk = blockIdx.x;
    int b = blk / HH, y = blk % HH;
    int t = threadIdx.x;

    const float* src = x + (size_t)(b*CC)*NPIX + y*WW;
    for (int i = t; i < CC*WW; i += 256) {
        int ci = i / WW, xx = i % WW;
        sh[ci*225 + xx] = src[(size_t)ci*NPIX + xx];
    }
    __syncthreads();

    size_t obase = (size_t)(b*HH + y) * (WW*CC);
    for (int j = t; j < WW*CC; j += 256) {
        int ci = j & 31, xx = j >> 5;
        float v = sh[ci*225 + xx];
        __nv_bfloat16 h = __float2bfloat16(v);
        float r = v - __bfloat162float(h);
        __nv_bfloat16 m = __float2bfloat16(r);
        float r2 = r - __bfloat162float(m);
        __nv_bfloat16 l = __float2bfloat16(r2);
        g_hx[obase + j] = ((__nv_bfloat16_raw)h).x;
        g_mx[obase + j] = ((__nv_bfloat16_raw)m).x;
        g_lx[obase + j] = ((__nv_bfloat16_raw)l).x;
    }
}

// ---------------------------------------------------------------------------
// PTX helpers (baseline PTX: sm_75/sm_80 features, fine on compute_103)
// ---------------------------------------------------------------------------
__device__ __forceinline__ uint32_t s2u(const void* p) {
    uint32_t a;
    asm("{ .reg .u64 t; cvta.to.shared.u64 t, %1; cvt.u32.u64 %0, t; }" : "=r"(a) : "l"(p));
    return a;
}
__device__ __forceinline__ void ldsm4(uint32_t* r, uint32_t addr) {
    asm volatile("ldmatrix.sync.aligned.m8n8.x4.shared.b16 {%0,%1,%2,%3}, [%4];"
                 : "=r"(r[0]), "=r"(r[1]), "=r"(r[2]), "=r"(r[3]) : "r"(addr));
}
// d += a*b (fragment MMA, accumulate into given float4)
__device__ __forceinline__ void mma_acc(float* d, const uint32_t* a, uint32_t b0, uint32_t b1) {
    asm volatile(
        "mma.sync.aligned.m16n8k16.row.col.f32.bf16.bf16.f32 "
        "{%0,%1,%2,%3}, {%4,%5,%6,%7}, {%8,%9}, {%0,%1,%2,%3};"
        : "+f"(d[0]), "+f"(d[1]), "+f"(d[2]), "+f"(d[3])
        : "r"(a[0]), "r"(a[1]), "r"(a[2]), "r"(a[3]), "r"(b0), "r"(b1));
}
__device__ __forceinline__ int lut_level(float v, float t0, float df) {
    int lev = 0;
    float th = t0;
    #pragma unroll
    for (int j = 0; j < 7; j++) {
        lev += (j & 1) ? (v >= th) : (v > th);   // validated compare chain
        th += df;
    }
    return lev;
}
__device__ __forceinline__ unsigned int bf16bits_of_int(int lev) {
    __nv_bfloat16 h = __float2bfloat16((float)lev);   // 0..7 exact
    return (unsigned int)((__nv_bfloat16_raw)h).x;
}

// ---------------------------------------------------------------------------
// Persistent fused conv3x3(pad=1, +-1 weights) + LUT via mma.sync bf16 HMMA.
// EXACT R14 structure; single delta: the im2col build uses a coalesced lane
// mapping (part = lane>>3, pixel = pb*8 + (lane&7)) — a pure permutation of
// R14's element transfers. Warp LDG: 512 contiguous bytes -> 4 wavefronts
// (was 16). STS words: 20*(lane&7) + 4*(lane>>3) mod 32 -> distinct within
// every 8-lane phase (conflict-free; pb*8*148 = 0 mod 32 drops out).
// ---------------------------------------------------------------------------
template<int STAGE>
__global__ __launch_bounds__(256, 2)
void conv_mma_kernel(float* __restrict__ outp)
{
    extern __shared__ char smc[];
    float*          lut = (float*)(smc + LUT_OFF);
    unsigned short* Bs  = (unsigned short*)(smc + B_OFF);
    unsigned short* As  = (unsigned short*)(smc + A_OFF);
    float*          Df  = (float*)(smc + A_OFF);     // stage-1 bounce (reuses A)

    const int tid   = threadIdx.x;
    const int wid   = tid >> 5;
    const int lane  = tid & 31;
    const int g     = lane >> 2;       // groupID (row / n)
    const int tg    = lane & 3;        // threadID_in_group (col pair)

    // stage B + LUT into smem (verbatim R14)
    {
        const uint32_t* gb = (const uint32_t*)(STAGE == 0 ? g_B1 : g_B2);
        uint32_t* bs32 = (uint32_t*)Bs;
        for (int i = tid; i < 32*144; i += 256) {
            int co = i / 144, j = i - co*144;
            bs32[co*(KP/2) + j] = gb[co*144 + j];
        }
        const float* gl = (STAGE == 0) ? g_lut1 : g_lut2;
        if (tid < 64) lut[tid] = gl[tid];
    }
    __syncthreads();

    // per-lane LUT regs: co(nt,i) = nt*8 + 2*tg + i  (verbatim R14)
    float t0r[8], dfr[8];
    #pragma unroll
    for (int nt = 0; nt < 4; nt++) {
        #pragma unroll
        for (int i = 0; i < 2; i++) {
            int co = nt*8 + 2*tg + i;
            t0r[nt*2+i] = lut[co];
            dfr[nt*2+i] = lut[32+co];
        }
    }

    // ldmatrix lane-address setup (verbatim R14).
    const uint32_t sbA = s2u(As);
    const uint32_t sbB = s2u(Bs);
    const uint32_t abase = sbA
        + (uint32_t)((wid*16 + (lane & 15))*KP + ((lane >> 4) * 8)) * 2;
    const int nrow = (lane & 7) + ((lane >> 4) << 3);
    const uint32_t bbase0 = sbB + (uint32_t)(nrow*KP + (((lane >> 3) & 1) * 8)) * 2;
    const uint32_t bbase1 = bbase0 + (uint32_t)(16*KP*2);

    // coalesced-build lane roles
    const int bl_part = lane >> 3;     // 16B chunk of the 64B pixel record
    const int bl_pxi  = lane & 7;      // pixel within 8-pixel block

    for (int t = blockIdx.x; t < NTILES; t += gridDim.x) {
        const int b  = t / (HH*2);
        const int rr = t % (HH*2);
        const int y  = rr >> 1;
        const int x0 = (rr & 1) * 96;
        const int nsub = (STAGE == 0) ? 3 : 1;

        float acc[4][4];
        #pragma unroll
        for (int nt = 0; nt < 4; nt++)
            #pragma unroll
            for (int c = 0; c < 4; c++) acc[nt][c] = 0.f;

        for (int sub = 0; sub < nsub; sub++) {
            const unsigned short* src;
            if (STAGE == 0) src = (sub == 0) ? g_hx : (sub == 1) ? g_mx : g_lx;
            else            src = g_lev;
            const unsigned short* srcb = src + (size_t)b * CL_PLANE;

            // ---- im2col build, coalesced mapping ----
            // 144 warp-items = 9 taps x 16 pixel-blocks; warp handles one
            // (tap, block) per iteration: 8 px x 4 parts = 512 contiguous B.
            #pragma unroll
            for (int it = 0; it < 18; it++) {
                const int j   = it*8 + wid;      // 0..143
                const int tap = j >> 4;          // 0..8
                const int pb  = j & 15;          // 0..15
                const int ky  = tap / 3, kx = tap - ky*3;
                const int pixel = pb*8 + bl_pxi;
                const int gy = y  + ky - 1;
                const int gx = x0 + pixel + kx - 1;
                uint4 v = make_uint4(0,0,0,0);
                if ((unsigned)gy < HH && (unsigned)gx < WW)
                    v = *(const uint4*)(srcb + (((size_t)gy*WW + gx) << 5) + bl_part*8);
                *(uint4*)(As + pixel*KP + tap*32 + bl_part*8) = v;
            }
            __syncthreads();

            // ---- 18 k-steps as 9 pairs of m16n8k16 (verbatim R14) ----
            #pragma unroll
            for (int sp = 0; sp < 9; sp++) {
                const uint32_t o0 = (uint32_t)(2*sp)     * 32;
                const uint32_t o1 = (uint32_t)(2*sp + 1) * 32;
                uint32_t A0[4], A1[4], B0[8], B1[8];
                ldsm4(A0, abase + o0);
                ldsm4(A1, abase + o1);
                ldsm4(B0 + 0, bbase0 + o0);  ldsm4(B0 + 4, bbase1 + o0);
                ldsm4(B1 + 0, bbase0 + o1);  ldsm4(B1 + 4, bbase1 + o1);
                #pragma unroll
                for (int nt = 0; nt < 4; nt++) {
                    if (STAGE == 1) {
                        mma_acc(acc[nt], A0, B0[nt*2], B0[nt*2+1]);
                        mma_acc(acc[nt], A1, B1[nt*2], B1[nt*2+1]);
                    } else {
                        float d[4] = {0.f, 0.f, 0.f, 0.f};
                        mma_acc(d, A0, B0[nt*2], B0[nt*2+1]);
                        mma_acc(d, A1, B1[nt*2], B1[nt*2+1]);
                        acc[nt][0] += d[0]; acc[nt][1] += d[1];
                        acc[nt][2] += d[2]; acc[nt][3] += d[3];
                    }
                }
            }
            __syncthreads();   // all warps done reading A before next build
        }

        // ---- epilogue (verbatim R14) ----
        const int p0 = wid*16 + g;     // D rows for c0/c1
        const int p1 = p0 + 8;         // D rows for c2/c3
        if (STAGE == 0) {
            size_t base0 = (size_t)b*CL_PLANE + (((size_t)y*WW + x0 + p0) << 5);
            size_t base1 = (size_t)b*CL_PLANE + (((size_t)y*WW + x0 + p1) << 5);
            #pragma unroll
            for (int nt = 0; nt < 4; nt++) {
                int l00 = lut_level(acc[nt][0], t0r[nt*2+0], dfr[nt*2+0]);
                int l01 = lut_level(acc[nt][1], t0r[nt*2+1], dfr[nt*2+1]);
                int l10 = lut_level(acc[nt][2], t0r[nt*2+0], dfr[nt*2+0]);
                int l11 = lut_level(acc[nt][3], t0r[nt*2+1], dfr[nt*2+1]);
                *(uint32_t*)(g_lev + base0 + nt*8 + 2*tg) =
                    bf16bits_of_int(l00) | (bf16bits_of_int(l01) << 16);
                *(uint32_t*)(g_lev + base1 + nt*8 + 2*tg) =
                    bf16bits_of_int(l10) | (bf16bits_of_int(l11) << 16);
            }
        } else {
            // bounce through smem as [co][DF_PITCH] for coalesced NCHW stores
            #pragma unroll
            for (int nt = 0; nt < 4; nt++) {
                int c0 = nt*8 + 2*tg, c1 = c0 + 1;
                Df[c0*DF_PITCH + p0] = (float)lut_level(acc[nt][0], t0r[nt*2+0], dfr[nt*2+0]);
                Df[c1*DF_PITCH + p0] = (float)lut_level(acc[nt][1], t0r[nt*2+1], dfr[nt*2+1]);
                Df[c0*DF_PITCH + p1] = (float)lut_level(acc[nt][2], t0r[nt*2+0], dfr[nt*2+0]);
                Df[c1*DF_PITCH + p1] = (float)lut_level(acc[nt][3], t0r[nt*2+1], dfr[nt*2+1]);
            }
            __syncthreads();
            {
                int co = tid >> 3, ch = tid & 7;
                int px = ch * 16;
                const uint4* s4 = (const uint4*)(Df + co*DF_PITCH + px);
                uint4* o4 = (uint4*)(outp + (size_t)b*CC*NPIX + (size_t)co*NPIX
                                          + (size_t)y*WW + x0 + px);
                o4[0] = s4[0]; o4[1] = s4[1]; o4[2] = s4[2]; o4[3] = s4[3];
            }
            __syncthreads();   // Df region becomes A again next tile
        }
    }
}

// ---------------------------------------------------------------------------
extern "C" void kernel_launch(void* const* d_in, const int* in_sizes, int n_in,
                              void* d_out, int out_size)
{
    const float* x    = (const float*)d_in[0];
    const float* w1   = (const float*)d_in[1];
    const float* w2   = (const float*)d_in[2];
    const float* bn1w = (const float*)d_in[3];
    const float* bn1b = (const float*)d_in[4];
    const float* bn1m = (const float*)d_in[5];
    const float* bn1v = (const float*)d_in[6];
    const float* bn2w = (const float*)d_in[7];
    const float* bn2b = (const float*)d_in[8];
    const float* bn2m = (const float*)d_in[9];
    const float* bn2v = (const float*)d_in[10];
    const float* a1   = (const float*)d_in[11];
    const float* a2   = (const float*)d_in[12];
    const float* ns   = (const float*)d_in[13];

    prep_kernel<<<1, 256>>>(w1, w2, bn1w, bn1b, bn1m, bn1v,
                            bn2w, bn2b, bn2m, bn2v, a1, a2, ns);
    split_kernel<<<BB*HH, 256>>>(x);

    cudaFuncSetAttribute(conv_mma_kernel<0>, cudaFuncAttributeMaxDynamicSharedMemorySize, SMEM_BYTES);
    cudaFuncSetAttribute(conv_mma_kernel<1>, cudaFuncAttributeMaxDynamicSharedMemorySize, SMEM_BYTES);

    conv_mma_kernel<0><<<296, 256, SMEM_BYTES>>>(nullptr);
    conv_mma_kernel<1><<<296, 256, SMEM_BYTES>>>((float*)d_out);
}